// round 1
// baseline (speedup 1.0000x reference)
#include <cuda_runtime.h>
#include <cstdint>

// Problem constants
#define Bn 16
#define Hn 512
#define Wn 512
#define Rr 8            // radius
#define SEG 64          // rows per block for vertical-sliding kernels
static constexpr size_t FSZ = (size_t)Bn * Hn * Wn;   // 4,194,304 elems per single-channel field

// Scratch (allocation-free rule: static __device__ globals)
__device__ float g_bufA[10 * FSZ];   // vertical sums of {g_r,g_g,g_b, gray, g*i x3, g*g x3}
__device__ float g_bufB[6 * FSZ];    // horizontal sums of {a_r,a_g,a_b, b_r,b_g,b_b}

__device__ __forceinline__ void fields_at(const float* __restrict__ xb, int h, float f[10]) {
    const size_t ch = (size_t)Hn * Wn;
    size_t o = (size_t)h * Wn;
    float xr = __ldg(xb + o);
    float xg = __ldg(xb + o + ch);
    float xv = __ldg(xb + o + 2 * ch);
    float gr = __saturatef(fmaf(xr, 0.229f, 0.485f));
    float gg = __saturatef(fmaf(xg, 0.224f, 0.456f));
    float gb = __saturatef(fmaf(xv, 0.225f, 0.406f));
    float gy = (gr + gg + gb) * (1.0f / 3.0f);
    f[0] = gr; f[1] = gg; f[2] = gb; f[3] = gy;
    f[4] = gr * gy; f[5] = gg * gy; f[6] = gb * gy;
    f[7] = gr * gr; f[8] = gg * gg; f[9] = gb * gb;
}

// ---------------- Kernel A: vertical box-sum of 10 fields (fused normalize) ----------------
__global__ void __launch_bounds__(128) kA(const float* __restrict__ x) {
    const int w  = blockIdx.x * 128 + threadIdx.x;
    const int b  = blockIdx.z;
    const int h0 = blockIdx.y * SEG;
    const float* xb = x + (size_t)b * 3 * Hn * Wn + w;

    float s[10];
#pragma unroll
    for (int i = 0; i < 10; ++i) s[i] = 0.0f;

    // preload window rows [h0-8, h0+7]
    for (int h = h0 - Rr; h < h0 + Rr; ++h) {
        if (h >= 0) {
            float f[10]; fields_at(xb, h, f);
#pragma unroll
            for (int i = 0; i < 10; ++i) s[i] += f[i];
        }
    }
    for (int h = h0; h < h0 + SEG; ++h) {
        int he = h + Rr;
        if (he < Hn) {
            float f[10]; fields_at(xb, he, f);
#pragma unroll
            for (int i = 0; i < 10; ++i) s[i] += f[i];
        }
        size_t o = ((size_t)b * Hn + h) * Wn + w;
#pragma unroll
        for (int i = 0; i < 10; ++i) g_bufA[(size_t)i * FSZ + o] = s[i];
        int hl = h - Rr;
        if (hl >= 0) {
            float f[10]; fields_at(xb, hl, f);
#pragma unroll
            for (int i = 0; i < 10; ++i) s[i] -= f[i];
        }
    }
}

// ---------------- Kernel B: horizontal sums -> a,b -> horizontal sums of a,b ----------------
// One image row per block. Skewed smem index kills the 4-way bank conflicts of
// blocked sliding windows.
#define SIDX(p) ((p) + ((p) >> 5))
#define SPAD 545   // SIDX(543 max) fits

__global__ void __launch_bounds__(128) kB() {
    __shared__ float sf[10][SPAD];
    __shared__ float ab[6][SPAD];
    const int h = blockIdx.x;
    const int b = blockIdx.y;
    const int tid = threadIdx.x;
    const size_t row = ((size_t)b * Hn + h) * Wn;

#pragma unroll
    for (int f = 0; f < 10; ++f) {
#pragma unroll
        for (int j = 0; j < 4; ++j) {
            int wdx = tid + j * 128;
            sf[f][SIDX(wdx + 8)] = g_bufA[(size_t)f * FSZ + row + wdx];
        }
    }
    if (tid < 8) {
#pragma unroll
        for (int f = 0; f < 10; ++f) { sf[f][SIDX(tid)] = 0.0f; sf[f][SIDX(520 + tid)] = 0.0f; }
#pragma unroll
        for (int f = 0; f < 6; ++f)  { ab[f][SIDX(tid)] = 0.0f; ab[f][SIDX(520 + tid)] = 0.0f; }
    }
    __syncthreads();

    const int w0 = tid * 4;
    float S[10];
#pragma unroll
    for (int f = 0; f < 10; ++f) {
        float acc = 0.0f;
#pragma unroll
        for (int j = 0; j < 17; ++j) acc += sf[f][SIDX(w0 + j)];
        S[f] = acc;
    }

    const float AREA  = 289.0f;
    const float INVA  = 1.0f / 289.0f;
    const float EPSA2 = 289.0f * 289.0f * 0.001f;   // eps * area^2

#pragma unroll
    for (int q = 0; q < 4; ++q) {
        int col = w0 + q;
        float Si = S[3];
#pragma unroll
        for (int c = 0; c < 3; ++c) {
            float Sg  = S[c];
            float num = fmaf(AREA, S[4 + c], -Sg * Si);
            float den = fmaf(AREA, S[7 + c], -Sg * Sg) + EPSA2;
            float a   = num / den;
            float bb  = (Si - a * Sg) * INVA;
            ab[c][SIDX(col + 8)]     = a;
            ab[3 + c][SIDX(col + 8)] = bb;
        }
        if (q < 3) {
#pragma unroll
            for (int f = 0; f < 10; ++f)
                S[f] += sf[f][SIDX(col + 17)] - sf[f][SIDX(col)];
        }
    }
    __syncthreads();

    float T[6];
#pragma unroll
    for (int f = 0; f < 6; ++f) {
        float acc = 0.0f;
#pragma unroll
        for (int j = 0; j < 17; ++j) acc += ab[f][SIDX(w0 + j)];
        T[f] = acc;
    }
#pragma unroll
    for (int q = 0; q < 4; ++q) {
        int col = w0 + q;
#pragma unroll
        for (int f = 0; f < 6; ++f)
            g_bufB[(size_t)f * FSZ + row + col] = T[f];
        if (q < 3) {
#pragma unroll
            for (int f = 0; f < 6; ++f)
                T[f] += ab[f][SIDX(col + 17)] - ab[f][SIDX(col)];
        }
    }
}

// ---------------- Kernel D: vertical sums of a,b + final combine ----------------
__global__ void __launch_bounds__(128) kD(const float* __restrict__ x, float* __restrict__ out) {
    const int w  = blockIdx.x * 128 + threadIdx.x;
    const int b  = blockIdx.z;
    const int h0 = blockIdx.y * SEG;
    const size_t ch = (size_t)Hn * Wn;
    const size_t base = (size_t)b * Hn * Wn + w;

    float s[6];
#pragma unroll
    for (int i = 0; i < 6; ++i) s[i] = 0.0f;

    for (int h = h0 - Rr; h < h0 + Rr; ++h) {
        if (h >= 0) {
            size_t o = base + (size_t)h * Wn;
#pragma unroll
            for (int i = 0; i < 6; ++i) s[i] += __ldg(&g_bufB[(size_t)i * FSZ + o]);
        }
    }

    const float* xb = x + (size_t)b * 3 * ch + w;
    float* ob = out + (size_t)b * 3 * ch + w;
    const float INVA = 1.0f / 289.0f;

    for (int h = h0; h < h0 + SEG; ++h) {
        int he = h + Rr;
        if (he < Hn) {
            size_t o = base + (size_t)he * Wn;
#pragma unroll
            for (int i = 0; i < 6; ++i) s[i] += __ldg(&g_bufB[(size_t)i * FSZ + o]);
        }
        size_t o = (size_t)h * Wn;
        float xr = __ldg(xb + o);
        float xg = __ldg(xb + o + ch);
        float xv = __ldg(xb + o + 2 * ch);
        float gr = __saturatef(fmaf(xr, 0.229f, 0.485f));
        float gg = __saturatef(fmaf(xg, 0.224f, 0.456f));
        float gb = __saturatef(fmaf(xv, 0.225f, 0.406f));
        ob[o]          = gr - fmaf(s[0] * INVA, gr, s[3] * INVA);
        ob[o + ch]     = gg - fmaf(s[1] * INVA, gg, s[4] * INVA);
        ob[o + 2 * ch] = gb - fmaf(s[2] * INVA, gb, s[5] * INVA);
        int hl = h - Rr;
        if (hl >= 0) {
            size_t o2 = base + (size_t)hl * Wn;
#pragma unroll
            for (int i = 0; i < 6; ++i) s[i] -= __ldg(&g_bufB[(size_t)i * FSZ + o2]);
        }
    }
}

extern "C" void kernel_launch(void* const* d_in, const int* in_sizes, int n_in,
                              void* d_out, int out_size) {
    const float* x = (const float*)d_in[0];
    float* out = (float*)d_out;
    (void)in_sizes; (void)n_in; (void)out_size;

    dim3 gA(Wn / 128, Hn / SEG, Bn);
    kA<<<gA, 128>>>(x);
    dim3 gB(Hn, Bn);
    kB<<<gB, 128>>>();
    kD<<<gA, 128>>>(x, out);
}

// round 2
// speedup vs baseline: 1.4071x; 1.4071x over previous
#include <cuda_runtime.h>
#include <cstdint>

#define Bn 16
#define Hn 512
#define Wn 512
#define Rr 8
#define SEG1 8          // output rows per block in fused kernel
#define SEGD 16         // rows per block in kD
static constexpr size_t FSZ = (size_t)Bn * Hn * Wn;

// Scratch: horizontally-summed a,b (6 fields)
__device__ float g_bufB[6 * FSZ];

#define SIDX(p) ((p) + ((p) >> 5))
#define SPAD 545

// 9 fields: 0-2 = g_rgb, 3-5 = g*gray, 6-8 = g*g   (gray sum derived as (S0+S1+S2)/3)
__device__ __forceinline__ void fields9(const float* __restrict__ xb, int h, int w, float f[9]) {
    const size_t ch = (size_t)Hn * Wn;
    size_t o = (size_t)h * Wn + w;
    float xr = __ldg(xb + o);
    float xg = __ldg(xb + o + ch);
    float xv = __ldg(xb + o + 2 * ch);
    float gr = __saturatef(fmaf(xr, 0.229f, 0.485f));
    float gg = __saturatef(fmaf(xg, 0.224f, 0.456f));
    float gb = __saturatef(fmaf(xv, 0.225f, 0.406f));
    float gy = (gr + gg + gb) * (1.0f / 3.0f);
    f[0] = gr; f[1] = gg; f[2] = gb;
    f[3] = gr * gy; f[4] = gg * gy; f[5] = gb * gy;
    f[6] = gr * gr; f[7] = gg * gg; f[8] = gb * gb;
}

// ---------------- Fused kernel: vertical sums (regs) + horizontal pass + a,b + horizontal sum of a,b ----
__global__ void __launch_bounds__(128) kF(const float* __restrict__ x) {
    __shared__ float sf[9][SPAD];
    __shared__ float ab[6][SPAD];
    const int tid = threadIdx.x;
    const int h0  = blockIdx.x * SEG1;
    const int b   = blockIdx.y;
    const float* xb = x + (size_t)b * 3 * Hn * Wn;

    // zero smem halos once (interior never touches them)
    if (tid < 8) {
#pragma unroll
        for (int f = 0; f < 9; ++f) { sf[f][SIDX(tid)] = 0.0f; sf[f][SIDX(520 + tid)] = 0.0f; }
#pragma unroll
        for (int f = 0; f < 6; ++f) { ab[f][SIDX(tid)] = 0.0f; ab[f][SIDX(520 + tid)] = 0.0f; }
    }

    float vs[9][4];
#pragma unroll
    for (int f = 0; f < 9; ++f)
#pragma unroll
        for (int j = 0; j < 4; ++j) vs[f][j] = 0.0f;

    // preload window rows [h0-8, h0+7]
    for (int h = h0 - Rr; h < h0 + Rr; ++h) {
        if (h >= 0) {
#pragma unroll
            for (int j = 0; j < 4; ++j) {
                float f[9]; fields9(xb, h, tid + 128 * j, f);
#pragma unroll
                for (int i = 0; i < 9; ++i) vs[i][j] += f[i];
            }
        }
    }
    __syncthreads();   // halo zeros visible

    const float AREA  = 289.0f;
    const float INVA  = 1.0f / 289.0f;
    const float EPSA2 = 289.0f * 289.0f * 0.001f;

    for (int h = h0; h < h0 + SEG1; ++h) {
        int he = h + Rr;
        if (he < Hn) {
#pragma unroll
            for (int j = 0; j < 4; ++j) {
                float f[9]; fields9(xb, he, tid + 128 * j, f);
#pragma unroll
                for (int i = 0; i < 9; ++i) vs[i][j] += f[i];
            }
        }
        // publish vertical sums
#pragma unroll
        for (int f = 0; f < 9; ++f)
#pragma unroll
            for (int j = 0; j < 4; ++j)
                sf[f][SIDX(tid + 128 * j + 8)] = vs[f][j];
        __syncthreads();

        // horizontal pass: 4 outputs per thread, blocked
        const int w0 = tid * 4;
        float S[9];
#pragma unroll
        for (int f = 0; f < 9; ++f) {
            float acc = 0.0f;
#pragma unroll
            for (int j = 0; j < 17; ++j) acc += sf[f][SIDX(w0 + j)];
            S[f] = acc;
        }
#pragma unroll
        for (int q = 0; q < 4; ++q) {
            int col = w0 + q;
            float Si = (S[0] + S[1] + S[2]) * (1.0f / 3.0f);
#pragma unroll
            for (int c = 0; c < 3; ++c) {
                float Sg  = S[c];
                float num = fmaf(AREA, S[3 + c], -Sg * Si);
                float den = fmaf(AREA, S[6 + c], -Sg * Sg) + EPSA2;
                float a   = num / den;
                float bb  = (Si - a * Sg) * INVA;
                ab[c][SIDX(col + 8)]     = a;
                ab[3 + c][SIDX(col + 8)] = bb;
            }
            if (q < 3) {
#pragma unroll
                for (int f = 0; f < 9; ++f)
                    S[f] += sf[f][SIDX(col + 17)] - sf[f][SIDX(col)];
            }
        }
        __syncthreads();

        // horizontal sums of a,b -> global
        float T[6];
#pragma unroll
        for (int f = 0; f < 6; ++f) {
            float acc = 0.0f;
#pragma unroll
            for (int j = 0; j < 17; ++j) acc += ab[f][SIDX(w0 + j)];
            T[f] = acc;
        }
        size_t row = ((size_t)b * Hn + h) * Wn;
#pragma unroll
        for (int q = 0; q < 4; ++q) {
            int col = w0 + q;
#pragma unroll
            for (int f = 0; f < 6; ++f)
                g_bufB[(size_t)f * FSZ + row + col] = T[f];
            if (q < 3) {
#pragma unroll
                for (int f = 0; f < 6; ++f)
                    T[f] += ab[f][SIDX(col + 17)] - ab[f][SIDX(col)];
            }
        }

        int hl = h - Rr;
        if (hl >= 0) {
#pragma unroll
            for (int j = 0; j < 4; ++j) {
                float f[9]; fields9(xb, hl, tid + 128 * j, f);
#pragma unroll
                for (int i = 0; i < 9; ++i) vs[i][j] -= f[i];
            }
        }
        __syncthreads();   // protect sf/ab overwrite next iteration
    }
}

// ---------------- Kernel D: vertical sums of a,b + final combine ----------------
__global__ void __launch_bounds__(128) kD(const float* __restrict__ x, float* __restrict__ out) {
    const int w  = blockIdx.x * 128 + threadIdx.x;
    const int b  = blockIdx.z;
    const int h0 = blockIdx.y * SEGD;
    const size_t ch = (size_t)Hn * Wn;
    const size_t base = (size_t)b * Hn * Wn + w;

    float s[6];
#pragma unroll
    for (int i = 0; i < 6; ++i) s[i] = 0.0f;

    for (int h = h0 - Rr; h < h0 + Rr; ++h) {
        if (h >= 0) {
            size_t o = base + (size_t)h * Wn;
#pragma unroll
            for (int i = 0; i < 6; ++i) s[i] += __ldg(&g_bufB[(size_t)i * FSZ + o]);
        }
    }

    const float* xb = x + (size_t)b * 3 * ch + w;
    float* ob = out + (size_t)b * 3 * ch + w;
    const float INVA = 1.0f / 289.0f;

    for (int h = h0; h < h0 + SEGD; ++h) {
        int he = h + Rr;
        if (he < Hn) {
            size_t o = base + (size_t)he * Wn;
#pragma unroll
            for (int i = 0; i < 6; ++i) s[i] += __ldg(&g_bufB[(size_t)i * FSZ + o]);
        }
        size_t o = (size_t)h * Wn;
        float xr = __ldg(xb + o);
        float xg = __ldg(xb + o + ch);
        float xv = __ldg(xb + o + 2 * ch);
        float gr = __saturatef(fmaf(xr, 0.229f, 0.485f));
        float gg = __saturatef(fmaf(xg, 0.224f, 0.456f));
        float gb = __saturatef(fmaf(xv, 0.225f, 0.406f));
        ob[o]          = gr - fmaf(s[0] * INVA, gr, s[3] * INVA);
        ob[o + ch]     = gg - fmaf(s[1] * INVA, gg, s[4] * INVA);
        ob[o + 2 * ch] = gb - fmaf(s[2] * INVA, gb, s[5] * INVA);
        int hl = h - Rr;
        if (hl >= 0) {
            size_t o2 = base + (size_t)hl * Wn;
#pragma unroll
            for (int i = 0; i < 6; ++i) s[i] -= __ldg(&g_bufB[(size_t)i * FSZ + o2]);
        }
    }
}

extern "C" void kernel_launch(void* const* d_in, const int* in_sizes, int n_in,
                              void* d_out, int out_size) {
    const float* x = (const float*)d_in[0];
    float* out = (float*)d_out;
    (void)in_sizes; (void)n_in; (void)out_size;

    dim3 gF(Hn / SEG1, Bn);
    kF<<<gF, 128>>>(x);
    dim3 gD(Wn / 128, Hn / SEGD, Bn);
    kD<<<gD, 128>>>(x, out);
}

// round 4
// speedup vs baseline: 2.2097x; 1.5704x over previous
#include <cuda_runtime.h>
#include <cstdint>

#define Bn 16
#define Hn 512
#define Wn 512
#define Rr 8
#define SEG1 8
#define SEGD 8
static constexpr size_t FSZ = (size_t)Bn * Hn * Wn;

__device__ float g_bufB[6 * FSZ];

#define SIDX(p) ((p) + ((p) >> 5))
#define SPAD 545
#define QPAD 132   // quads: idx = t+2, halo 0,1,130,131

// fields: 0-2 g_rgb, 3-5 g*gray, 6-8 g*g
template <bool SUB>
__device__ __forceinline__ void accum4(const float* __restrict__ xb, int h, int w0,
                                       float vs[9][4]) {
    const size_t ch = (size_t)Hn * Wn;
    size_t o = (size_t)h * Wn + w0;
    float4 x0 = __ldg((const float4*)(xb + o));
    float4 x1 = __ldg((const float4*)(xb + o + ch));
    float4 x2 = __ldg((const float4*)(xb + o + 2 * ch));
    float R[4] = {x0.x, x0.y, x0.z, x0.w};
    float G[4] = {x1.x, x1.y, x1.z, x1.w};
    float Bv[4] = {x2.x, x2.y, x2.z, x2.w};
#pragma unroll
    for (int c = 0; c < 4; ++c) {
        float gr = __saturatef(fmaf(R[c], 0.229f, 0.485f));
        float gg = __saturatef(fmaf(G[c], 0.224f, 0.456f));
        float gb = __saturatef(fmaf(Bv[c], 0.225f, 0.406f));
        float gy = (gr + gg + gb) * (1.0f / 3.0f);
        float f[9] = {gr, gg, gb, gr * gy, gg * gy, gb * gy, gr * gr, gg * gg, gb * gb};
#pragma unroll
        for (int i = 0; i < 9; ++i) {
            if (SUB) vs[i][c] -= f[i]; else vs[i][c] += f[i];
        }
    }
}

// ---------------- Fused kernel ----------------
__global__ void __launch_bounds__(128) kF(const float* __restrict__ x) {
    __shared__ float sraw[9][SPAD];
    __shared__ float squad[9][QPAD];
    __shared__ float araw[6][SPAD];
    __shared__ float aquad[6][QPAD];
    const int tid = threadIdx.x;
    const int h0  = blockIdx.x * SEG1;
    const int b   = blockIdx.y;
    const int w0  = tid * 4;
    const float* xb = x + (size_t)b * 3 * Hn * Wn;

    if (tid < 8) {
#pragma unroll
        for (int f = 0; f < 9; ++f) { sraw[f][SIDX(tid)] = 0.0f; sraw[f][SIDX(520 + tid)] = 0.0f; }
#pragma unroll
        for (int f = 0; f < 6; ++f) { araw[f][SIDX(tid)] = 0.0f; araw[f][SIDX(520 + tid)] = 0.0f; }
    }
    if (tid < 2) {
#pragma unroll
        for (int f = 0; f < 9; ++f) { squad[f][tid] = 0.0f; squad[f][130 + tid] = 0.0f; }
#pragma unroll
        for (int f = 0; f < 6; ++f) { aquad[f][tid] = 0.0f; aquad[f][130 + tid] = 0.0f; }
    }

    float vs[9][4];
#pragma unroll
    for (int f = 0; f < 9; ++f)
#pragma unroll
        for (int c = 0; c < 4; ++c) vs[f][c] = 0.0f;

    for (int h = h0 - Rr; h < h0 + Rr; ++h)
        if (h >= 0) accum4<false>(xb, h, w0, vs);
    __syncthreads();

    const float AREA  = 289.0f;
    const float INVA  = 1.0f / 289.0f;
    const float EPSA2 = 289.0f * 289.0f * 0.001f;

    for (int h = h0; h < h0 + SEG1; ++h) {
        int he = h + Rr;
        if (he < Hn) accum4<false>(xb, he, w0, vs);

        float qown[9];
#pragma unroll
        for (int f = 0; f < 9; ++f) {
#pragma unroll
            for (int c = 0; c < 4; ++c) sraw[f][SIDX(w0 + c + 8)] = vs[f][c];
            qown[f] = (vs[f][0] + vs[f][1]) + (vs[f][2] + vs[f][3]);
            squad[f][tid + 2] = qown[f];
        }
        __syncthreads();

        float S[9];
#pragma unroll
        for (int f = 0; f < 9; ++f)
            S[f] = ((squad[f][tid] + squad[f][tid + 1]) + (qown[f] + squad[f][tid + 3]))
                 + sraw[f][SIDX(w0 + 16)];

        float av[3][4], bv[3][4];
#pragma unroll
        for (int q = 0; q < 4; ++q) {
            float Si = (S[0] + S[1] + S[2]) * (1.0f / 3.0f);
#pragma unroll
            for (int c = 0; c < 3; ++c) {
                float Sg  = S[c];
                float num = fmaf(AREA, S[3 + c], -Sg * Si);
                float den = fmaf(AREA, S[6 + c], -Sg * Sg) + EPSA2;
                float a   = num / den;
                av[c][q] = a;
                bv[c][q] = (Si - a * Sg) * INVA;
            }
            if (q < 3) {
#pragma unroll
                for (int f = 0; f < 9; ++f)
                    S[f] += sraw[f][SIDX(w0 + q + 17)] - sraw[f][SIDX(w0 + q)];
            }
        }

        float qa[6];
#pragma unroll
        for (int c = 0; c < 3; ++c) {
#pragma unroll
            for (int k = 0; k < 4; ++k) {
                araw[c][SIDX(w0 + k + 8)]     = av[c][k];
                araw[3 + c][SIDX(w0 + k + 8)] = bv[c][k];
            }
            qa[c]     = (av[c][0] + av[c][1]) + (av[c][2] + av[c][3]);
            qa[3 + c] = (bv[c][0] + bv[c][1]) + (bv[c][2] + bv[c][3]);
            aquad[c][tid + 2]     = qa[c];
            aquad[3 + c][tid + 2] = qa[3 + c];
        }
        __syncthreads();

        float T[6];
#pragma unroll
        for (int f = 0; f < 6; ++f)
            T[f] = ((aquad[f][tid] + aquad[f][tid + 1]) + (qa[f] + aquad[f][tid + 3]))
                 + araw[f][SIDX(w0 + 16)];

        float tq[6][4];
#pragma unroll
        for (int q = 0; q < 4; ++q) {
#pragma unroll
            for (int f = 0; f < 6; ++f) tq[f][q] = T[f];
            if (q < 3) {
#pragma unroll
                for (int f = 0; f < 6; ++f)
                    T[f] += araw[f][SIDX(w0 + q + 17)] - araw[f][SIDX(w0 + q)];
            }
        }
        size_t row = ((size_t)b * Hn + h) * Wn + w0;
#pragma unroll
        for (int f = 0; f < 6; ++f)
            *(float4*)(&g_bufB[(size_t)f * FSZ + row]) =
                make_float4(tq[f][0], tq[f][1], tq[f][2], tq[f][3]);

        int hl = h - Rr;
        if (hl >= 0) accum4<true>(xb, hl, w0, vs);
        __syncthreads();
    }
}

// ---------------- Kernel D: vertical sums of a,b + final combine (float4) ----------------
__global__ void __launch_bounds__(128) kD(const float* __restrict__ x, float* __restrict__ out) {
    const int w0 = threadIdx.x * 4;
    const int b  = blockIdx.z;
    const int h0 = blockIdx.y * SEGD;
    const size_t ch = (size_t)Hn * Wn;
    const size_t base = (size_t)b * Hn * Wn + w0;

    float s[6][4];
#pragma unroll
    for (int i = 0; i < 6; ++i)
#pragma unroll
        for (int c = 0; c < 4; ++c) s[i][c] = 0.0f;

    for (int h = h0 - Rr; h < h0 + Rr; ++h) {
        if (h >= 0) {
            size_t o = base + (size_t)h * Wn;
#pragma unroll
            for (int i = 0; i < 6; ++i) {
                float4 v = __ldg((const float4*)(&g_bufB[(size_t)i * FSZ + o]));
                s[i][0] += v.x; s[i][1] += v.y; s[i][2] += v.z; s[i][3] += v.w;
            }
        }
    }

    const float* xb = x + (size_t)b * 3 * ch + w0;
    float* ob = out + (size_t)b * 3 * ch + w0;
    // a,b are true values; their (2r+1)^2-pixel sum needs one division by 289.
    const float INVA = 1.0f / 289.0f;

    for (int h = h0; h < h0 + SEGD; ++h) {
        int he = h + Rr;
        if (he < Hn) {
            size_t o = base + (size_t)he * Wn;
#pragma unroll
            for (int i = 0; i < 6; ++i) {
                float4 v = __ldg((const float4*)(&g_bufB[(size_t)i * FSZ + o]));
                s[i][0] += v.x; s[i][1] += v.y; s[i][2] += v.z; s[i][3] += v.w;
            }
        }
        size_t o = (size_t)h * Wn;
        float4 x0 = __ldg((const float4*)(xb + o));
        float4 x1 = __ldg((const float4*)(xb + o + ch));
        float4 x2 = __ldg((const float4*)(xb + o + 2 * ch));
        float R[4] = {x0.x, x0.y, x0.z, x0.w};
        float G[4] = {x1.x, x1.y, x1.z, x1.w};
        float Bv[4] = {x2.x, x2.y, x2.z, x2.w};
        float o0[4], o1[4], o2[4];
#pragma unroll
        for (int c = 0; c < 4; ++c) {
            float gr = __saturatef(fmaf(R[c], 0.229f, 0.485f));
            float gg = __saturatef(fmaf(G[c], 0.224f, 0.456f));
            float gb = __saturatef(fmaf(Bv[c], 0.225f, 0.406f));
            o0[c] = gr - fmaf(s[0][c], gr, s[3][c]) * INVA;
            o1[c] = gg - fmaf(s[1][c], gg, s[4][c]) * INVA;
            o2[c] = gb - fmaf(s[2][c], gb, s[5][c]) * INVA;
        }
        *(float4*)(ob + o)          = make_float4(o0[0], o0[1], o0[2], o0[3]);
        *(float4*)(ob + o + ch)     = make_float4(o1[0], o1[1], o1[2], o1[3]);
        *(float4*)(ob + o + 2 * ch) = make_float4(o2[0], o2[1], o2[2], o2[3]);
        int hl = h - Rr;
        if (hl >= 0) {
            size_t o2i = base + (size_t)hl * Wn;
#pragma unroll
            for (int i = 0; i < 6; ++i) {
                float4 v = __ldg((const float4*)(&g_bufB[(size_t)i * FSZ + o2i]));
                s[i][0] -= v.x; s[i][1] -= v.y; s[i][2] -= v.z; s[i][3] -= v.w;
            }
        }
    }
}

extern "C" void kernel_launch(void* const* d_in, const int* in_sizes, int n_in,
                              void* d_out, int out_size) {
    const float* x = (const float*)d_in[0];
    float* out = (float*)d_out;
    (void)in_sizes; (void)n_in; (void)out_size;

    dim3 gF(Hn / SEG1, Bn);
    kF<<<gF, 128>>>(x);
    dim3 gD(1, Hn / SEGD, Bn);
    kD<<<gD, 128>>>(x, out);
}

// round 5
// speedup vs baseline: 2.2388x; 1.0131x over previous
#include <cuda_runtime.h>
#include <cstdint>

#define Bn 16
#define Hn 512
#define Wn 512
#define Rr 8
#define SEG1 8
#define SEGD 16
static constexpr size_t FSZ = (size_t)Bn * Hn * Wn;

__device__ float g_bufB[6 * FSZ];

#define SIDX(p) ((p) + ((p) >> 5))
#define SPAD 545
#define QPAD 132

// fields: 0-2 g_rgb, 3-5 g*gray, 6-8 g*g
template <bool SUB>
__device__ __forceinline__ void accum4(const float* __restrict__ xb, int h, int w0,
                                       float vs[9][4]) {
    const size_t ch = (size_t)Hn * Wn;
    size_t o = (size_t)h * Wn + w0;
    float4 x0 = __ldg((const float4*)(xb + o));
    float4 x1 = __ldg((const float4*)(xb + o + ch));
    float4 x2 = __ldg((const float4*)(xb + o + 2 * ch));
    float R[4] = {x0.x, x0.y, x0.z, x0.w};
    float G[4] = {x1.x, x1.y, x1.z, x1.w};
    float Bv[4] = {x2.x, x2.y, x2.z, x2.w};
#pragma unroll
    for (int c = 0; c < 4; ++c) {
        float gr = __saturatef(fmaf(R[c], 0.229f, 0.485f));
        float gg = __saturatef(fmaf(G[c], 0.224f, 0.456f));
        float gb = __saturatef(fmaf(Bv[c], 0.225f, 0.406f));
        float gy = (gr + gg + gb) * (1.0f / 3.0f);
        float f[9] = {gr, gg, gb, gr * gy, gg * gy, gb * gy, gr * gr, gg * gg, gb * gb};
#pragma unroll
        for (int i = 0; i < 9; ++i) {
            if (SUB) vs[i][c] -= f[i]; else vs[i][c] += f[i];
        }
    }
}

// ---------------- Fused kernel (a/b smem aliased onto field smem) ----------------
__global__ void __launch_bounds__(128) kF(const float* __restrict__ x) {
    __shared__ float sraw[9][SPAD];
    __shared__ float squad[9][QPAD];
    // a/b phase reuses the first 6 field planes (phases separated by syncs)
    float (*araw)[SPAD] = sraw;
    float (*aquad)[QPAD] = squad;

    const int tid = threadIdx.x;
    const int h0  = blockIdx.x * SEG1;
    const int b   = blockIdx.y;
    const int w0  = tid * 4;
    const float* xb = x + (size_t)b * 3 * Hn * Wn;

    // halos: interior never writes idx<8 or >=520 (raw) / <2 or >=130 (quad),
    // so zeros persist for both the field phase and the aliased a/b phase.
    if (tid < 8) {
#pragma unroll
        for (int f = 0; f < 9; ++f) { sraw[f][SIDX(tid)] = 0.0f; sraw[f][SIDX(520 + tid)] = 0.0f; }
    }
    if (tid < 2) {
#pragma unroll
        for (int f = 0; f < 9; ++f) { squad[f][tid] = 0.0f; squad[f][130 + tid] = 0.0f; }
    }

    float vs[9][4];
#pragma unroll
    for (int f = 0; f < 9; ++f)
#pragma unroll
        for (int c = 0; c < 4; ++c) vs[f][c] = 0.0f;

    for (int h = h0 - Rr; h < h0 + Rr; ++h)
        if (h >= 0) accum4<false>(xb, h, w0, vs);
    __syncthreads();

    const float AREA  = 289.0f;
    const float INVA  = 1.0f / 289.0f;
    const float EPSA2 = 289.0f * 289.0f * 0.001f;

    for (int h = h0; h < h0 + SEG1; ++h) {
        int he = h + Rr;
        if (he < Hn) accum4<false>(xb, he, w0, vs);

        float qown[9];
#pragma unroll
        for (int f = 0; f < 9; ++f) {
#pragma unroll
            for (int c = 0; c < 4; ++c) sraw[f][SIDX(w0 + c + 8)] = vs[f][c];
            qown[f] = (vs[f][0] + vs[f][1]) + (vs[f][2] + vs[f][3]);
            squad[f][tid + 2] = qown[f];
        }
        __syncthreads();   // [A] publish fields

        float S[9];
#pragma unroll
        for (int f = 0; f < 9; ++f)
            S[f] = ((squad[f][tid] + squad[f][tid + 1]) + (qown[f] + squad[f][tid + 3]))
                 + sraw[f][SIDX(w0 + 16)];

        float av[3][4], bv[3][4];
#pragma unroll
        for (int q = 0; q < 4; ++q) {
            float Si = (S[0] + S[1] + S[2]) * (1.0f / 3.0f);
#pragma unroll
            for (int c = 0; c < 3; ++c) {
                float Sg  = S[c];
                float num = fmaf(AREA, S[3 + c], -Sg * Si);
                float den = fmaf(AREA, S[6 + c], -Sg * Sg) + EPSA2;
                float a   = num / den;
                av[c][q] = a;
                bv[c][q] = (Si - a * Sg) * INVA;
            }
            if (q < 3) {
#pragma unroll
                for (int f = 0; f < 9; ++f)
                    S[f] += sraw[f][SIDX(w0 + q + 17)] - sraw[f][SIDX(w0 + q)];
            }
        }
        __syncthreads();   // [B] all reads of sraw/squad done -> safe to alias

        float qa[6];
#pragma unroll
        for (int c = 0; c < 3; ++c) {
#pragma unroll
            for (int k = 0; k < 4; ++k) {
                araw[c][SIDX(w0 + k + 8)]     = av[c][k];
                araw[3 + c][SIDX(w0 + k + 8)] = bv[c][k];
            }
            qa[c]     = (av[c][0] + av[c][1]) + (av[c][2] + av[c][3]);
            qa[3 + c] = (bv[c][0] + bv[c][1]) + (bv[c][2] + bv[c][3]);
            aquad[c][tid + 2]     = qa[c];
            aquad[3 + c][tid + 2] = qa[3 + c];
        }
        __syncthreads();   // [C] publish a/b

        float T[6];
#pragma unroll
        for (int f = 0; f < 6; ++f)
            T[f] = ((aquad[f][tid] + aquad[f][tid + 1]) + (qa[f] + aquad[f][tid + 3]))
                 + araw[f][SIDX(w0 + 16)];

        float tq[6][4];
#pragma unroll
        for (int q = 0; q < 4; ++q) {
#pragma unroll
            for (int f = 0; f < 6; ++f) tq[f][q] = T[f];
            if (q < 3) {
#pragma unroll
                for (int f = 0; f < 6; ++f)
                    T[f] += araw[f][SIDX(w0 + q + 17)] - araw[f][SIDX(w0 + q)];
            }
        }
        size_t row = ((size_t)b * Hn + h) * Wn + w0;
#pragma unroll
        for (int f = 0; f < 6; ++f)
            *(float4*)(&g_bufB[(size_t)f * FSZ + row]) =
                make_float4(tq[f][0], tq[f][1], tq[f][2], tq[f][3]);

        int hl = h - Rr;
        if (hl >= 0) accum4<true>(xb, hl, w0, vs);
        __syncthreads();   // [D] a/b reads done -> next row may overwrite fields
    }
}

// ---------------- Kernel D: 512 threads, scalar, SEGD=16 ----------------
__global__ void __launch_bounds__(512) kD(const float* __restrict__ x, float* __restrict__ out) {
    const int w  = threadIdx.x;          // 0..511 (full row)
    const int b  = blockIdx.z;
    const int h0 = blockIdx.y * SEGD;
    const size_t ch = (size_t)Hn * Wn;
    const size_t base = (size_t)b * Hn * Wn + w;

    float s[6];
#pragma unroll
    for (int i = 0; i < 6; ++i) s[i] = 0.0f;

    for (int h = h0 - Rr; h < h0 + Rr; ++h) {
        if (h >= 0) {
            size_t o = base + (size_t)h * Wn;
#pragma unroll
            for (int i = 0; i < 6; ++i) s[i] += __ldg(&g_bufB[(size_t)i * FSZ + o]);
        }
    }

    const float* xb = x + (size_t)b * 3 * ch + w;
    float* ob = out + (size_t)b * 3 * ch + w;
    const float INVA = 1.0f / 289.0f;   // a,b are true values; one /289 for the mean

    for (int h = h0; h < h0 + SEGD; ++h) {
        int he = h + Rr;
        if (he < Hn) {
            size_t o = base + (size_t)he * Wn;
#pragma unroll
            for (int i = 0; i < 6; ++i) s[i] += __ldg(&g_bufB[(size_t)i * FSZ + o]);
        }
        size_t o = (size_t)h * Wn;
        float xr = __ldg(xb + o);
        float xg = __ldg(xb + o + ch);
        float xv = __ldg(xb + o + 2 * ch);
        float gr = __saturatef(fmaf(xr, 0.229f, 0.485f));
        float gg = __saturatef(fmaf(xg, 0.224f, 0.456f));
        float gb = __saturatef(fmaf(xv, 0.225f, 0.406f));
        ob[o]          = gr - fmaf(s[0], gr, s[3]) * INVA;
        ob[o + ch]     = gg - fmaf(s[1], gg, s[4]) * INVA;
        ob[o + 2 * ch] = gb - fmaf(s[2], gb, s[5]) * INVA;
        int hl = h - Rr;
        if (hl >= 0) {
            size_t o2 = base + (size_t)hl * Wn;
#pragma unroll
            for (int i = 0; i < 6; ++i) s[i] -= __ldg(&g_bufB[(size_t)i * FSZ + o2]);
        }
    }
}

extern "C" void kernel_launch(void* const* d_in, const int* in_sizes, int n_in,
                              void* d_out, int out_size) {
    const float* x = (const float*)d_in[0];
    float* out = (float*)d_out;
    (void)in_sizes; (void)n_in; (void)out_size;

    dim3 gF(Hn / SEG1, Bn);
    kF<<<gF, 128>>>(x);
    dim3 gD(1, Hn / SEGD, Bn);
    kD<<<gD, 512>>>(x, out);
}

// round 6
// speedup vs baseline: 2.6573x; 1.1870x over previous
#include <cuda_runtime.h>
#include <cuda_fp16.h>
#include <cstdint>

#define Bn 16
#define Hn 512
#define Wn 512
#define Rr 8
#define SEG1 8
#define SEGD 16
static constexpr size_t FSZ = (size_t)Bn * Hn * Wn;

// packed intermediate: per channel c, .x = 17-col sum of a_c, .y = 17-col sum of b_c
__device__ __half2 g_bufH[3 * FSZ];

#define SIDX(p) ((p) + ((p) >> 5))
#define SPAD 545
#define QPAD 132

// fields: 0-2 g_rgb, 3-5 g*gray, 6-8 g*g
template <bool SUB>
__device__ __forceinline__ void accum4(const float* __restrict__ xb, int h, int w0,
                                       float vs[9][4]) {
    const size_t ch = (size_t)Hn * Wn;
    size_t o = (size_t)h * Wn + w0;
    float4 x0 = __ldg((const float4*)(xb + o));
    float4 x1 = __ldg((const float4*)(xb + o + ch));
    float4 x2 = __ldg((const float4*)(xb + o + 2 * ch));
    float R[4] = {x0.x, x0.y, x0.z, x0.w};
    float G[4] = {x1.x, x1.y, x1.z, x1.w};
    float Bv[4] = {x2.x, x2.y, x2.z, x2.w};
#pragma unroll
    for (int c = 0; c < 4; ++c) {
        float gr = __saturatef(fmaf(R[c], 0.229f, 0.485f));
        float gg = __saturatef(fmaf(G[c], 0.224f, 0.456f));
        float gb = __saturatef(fmaf(Bv[c], 0.225f, 0.406f));
        float gy = (gr + gg + gb) * (1.0f / 3.0f);
        float f[9] = {gr, gg, gb, gr * gy, gg * gy, gb * gy, gr * gr, gg * gg, gb * gb};
#pragma unroll
        for (int i = 0; i < 9; ++i) {
            if (SUB) vs[i][c] -= f[i]; else vs[i][c] += f[i];
        }
    }
}

// ---------------- Fused kernel: 2 syncs per row ----------------
__global__ void __launch_bounds__(128) kF(const float* __restrict__ x) {
    __shared__ float sraw[9][SPAD];
    __shared__ float squad[9][QPAD];
    __shared__ float araw[6][SPAD];
    __shared__ float aquad[6][QPAD];

    const int tid = threadIdx.x;
    const int h0  = blockIdx.x * SEG1;
    const int b   = blockIdx.y;
    const int w0  = tid * 4;
    const float* xb = x + (size_t)b * 3 * Hn * Wn;

    if (tid < 8) {
#pragma unroll
        for (int f = 0; f < 9; ++f) { sraw[f][SIDX(tid)] = 0.0f; sraw[f][SIDX(520 + tid)] = 0.0f; }
#pragma unroll
        for (int f = 0; f < 6; ++f) { araw[f][SIDX(tid)] = 0.0f; araw[f][SIDX(520 + tid)] = 0.0f; }
    }
    if (tid < 2) {
#pragma unroll
        for (int f = 0; f < 9; ++f) { squad[f][tid] = 0.0f; squad[f][130 + tid] = 0.0f; }
#pragma unroll
        for (int f = 0; f < 6; ++f) { aquad[f][tid] = 0.0f; aquad[f][130 + tid] = 0.0f; }
    }

    float vs[9][4];
#pragma unroll
    for (int f = 0; f < 9; ++f)
#pragma unroll
        for (int c = 0; c < 4; ++c) vs[f][c] = 0.0f;

    for (int h = h0 - Rr; h < h0 + Rr; ++h)
        if (h >= 0) accum4<false>(xb, h, w0, vs);
    __syncthreads();

    const float AREA  = 289.0f;
    const float INVA  = 1.0f / 289.0f;
    const float EPSA2 = 289.0f * 289.0f * 0.001f;

    for (int h = h0; h < h0 + SEG1; ++h) {
        int he = h + Rr;
        if (he < Hn) accum4<false>(xb, he, w0, vs);

        // W1: publish fields (sraw/squad)
        float qown[9];
#pragma unroll
        for (int f = 0; f < 9; ++f) {
#pragma unroll
            for (int c = 0; c < 4; ++c) sraw[f][SIDX(w0 + c + 8)] = vs[f][c];
            qown[f] = (vs[f][0] + vs[f][1]) + (vs[f][2] + vs[f][3]);
            squad[f][tid + 2] = qown[f];
        }
        __syncthreads();   // S1  (also fences prev-iter R2 reads of araw vs this-iter W2)

        // R1: window assembly + slides + a/b math
        float S[9];
#pragma unroll
        for (int f = 0; f < 9; ++f)
            S[f] = ((squad[f][tid] + squad[f][tid + 1]) + (qown[f] + squad[f][tid + 3]))
                 + sraw[f][SIDX(w0 + 16)];

        float av[3][4], bv[3][4];
#pragma unroll
        for (int q = 0; q < 4; ++q) {
            float Si = (S[0] + S[1] + S[2]) * (1.0f / 3.0f);
#pragma unroll
            for (int c = 0; c < 3; ++c) {
                float Sg  = S[c];
                float num = fmaf(AREA, S[3 + c], -Sg * Si);
                float den = fmaf(AREA, S[6 + c], -Sg * Sg) + EPSA2;
                float a   = num / den;
                av[c][q] = a;
                bv[c][q] = (Si - a * Sg) * INVA;
            }
            if (q < 3) {
#pragma unroll
                for (int f = 0; f < 9; ++f)
                    S[f] += sraw[f][SIDX(w0 + q + 17)] - sraw[f][SIDX(w0 + q)];
            }
        }

        // W2: publish a/b (araw/aquad — disjoint from sraw/squad, no sync needed before)
        float qa[6];
#pragma unroll
        for (int c = 0; c < 3; ++c) {
#pragma unroll
            for (int k = 0; k < 4; ++k) {
                araw[c][SIDX(w0 + k + 8)]     = av[c][k];
                araw[3 + c][SIDX(w0 + k + 8)] = bv[c][k];
            }
            qa[c]     = (av[c][0] + av[c][1]) + (av[c][2] + av[c][3]);
            qa[3 + c] = (bv[c][0] + bv[c][1]) + (bv[c][2] + bv[c][3]);
            aquad[c][tid + 2]     = qa[c];
            aquad[3 + c][tid + 2] = qa[3 + c];
        }
        __syncthreads();   // S2  (also fences this-iter R1 reads of sraw vs next-iter W1)

        // R2: horizontal sums of a,b -> packed half2 -> global
        float T[6];
#pragma unroll
        for (int f = 0; f < 6; ++f)
            T[f] = ((aquad[f][tid] + aquad[f][tid + 1]) + (qa[f] + aquad[f][tid + 3]))
                 + araw[f][SIDX(w0 + 16)];

        __align__(16) __half2 pack[3][4];
#pragma unroll
        for (int q = 0; q < 4; ++q) {
#pragma unroll
            for (int c = 0; c < 3; ++c)
                pack[c][q] = __floats2half2_rn(T[c], T[3 + c]);
            if (q < 3) {
#pragma unroll
                for (int f = 0; f < 6; ++f)
                    T[f] += araw[f][SIDX(w0 + q + 17)] - araw[f][SIDX(w0 + q)];
            }
        }
        size_t row = ((size_t)b * Hn + h) * Wn + w0;
#pragma unroll
        for (int c = 0; c < 3; ++c)
            *(uint4*)(&g_bufH[(size_t)c * FSZ + row]) = *(const uint4*)(&pack[c][0]);

        int hl = h - Rr;
        if (hl >= 0) accum4<true>(xb, hl, w0, vs);
    }
}

// ---------------- Kernel D: vertical sums of packed T + final combine ----------------
__global__ void __launch_bounds__(512) kD(const float* __restrict__ x, float* __restrict__ out) {
    const int w  = threadIdx.x;
    const int b  = blockIdx.z;
    const int h0 = blockIdx.y * SEGD;
    const size_t ch = (size_t)Hn * Wn;
    const size_t base = (size_t)b * Hn * Wn + w;

    float sa[3], sb[3];
#pragma unroll
    for (int c = 0; c < 3; ++c) { sa[c] = 0.0f; sb[c] = 0.0f; }

    for (int h = h0 - Rr; h < h0 + Rr; ++h) {
        if (h >= 0) {
            size_t o = base + (size_t)h * Wn;
#pragma unroll
            for (int c = 0; c < 3; ++c) {
                float2 v = __half22float2(g_bufH[(size_t)c * FSZ + o]);
                sa[c] += v.x; sb[c] += v.y;
            }
        }
    }

    const float* xb = x + (size_t)b * 3 * ch + w;
    float* ob = out + (size_t)b * 3 * ch + w;
    const float INVA = 1.0f / 289.0f;

    for (int h = h0; h < h0 + SEGD; ++h) {
        int he = h + Rr;
        if (he < Hn) {
            size_t o = base + (size_t)he * Wn;
#pragma unroll
            for (int c = 0; c < 3; ++c) {
                float2 v = __half22float2(g_bufH[(size_t)c * FSZ + o]);
                sa[c] += v.x; sb[c] += v.y;
            }
        }
        size_t o = (size_t)h * Wn;
        float xr = __ldg(xb + o);
        float xg = __ldg(xb + o + ch);
        float xv = __ldg(xb + o + 2 * ch);
        float gr = __saturatef(fmaf(xr, 0.229f, 0.485f));
        float gg = __saturatef(fmaf(xg, 0.224f, 0.456f));
        float gb = __saturatef(fmaf(xv, 0.225f, 0.406f));
        ob[o]          = gr - fmaf(sa[0], gr, sb[0]) * INVA;
        ob[o + ch]     = gg - fmaf(sa[1], gg, sb[1]) * INVA;
        ob[o + 2 * ch] = gb - fmaf(sa[2], gb, sb[2]) * INVA;
        int hl = h - Rr;
        if (hl >= 0) {
            size_t o2 = base + (size_t)hl * Wn;
#pragma unroll
            for (int c = 0; c < 3; ++c) {
                float2 v = __half22float2(g_bufH[(size_t)c * FSZ + o2]);
                sa[c] -= v.x; sb[c] -= v.y;
            }
        }
    }
}

extern "C" void kernel_launch(void* const* d_in, const int* in_sizes, int n_in,
                              void* d_out, int out_size) {
    const float* x = (const float*)d_in[0];
    float* out = (float*)d_out;
    (void)in_sizes; (void)n_in; (void)out_size;

    dim3 gF(Hn / SEG1, Bn);
    kF<<<gF, 128>>>(x);
    dim3 gD(1, Hn / SEGD, Bn);
    kD<<<gD, 512>>>(x, out);
}

// round 7
// speedup vs baseline: 2.9841x; 1.1230x over previous
#include <cuda_runtime.h>
#include <cuda_fp16.h>
#include <cstdint>

#define Bn 16
#define Hn 512
#define Wn 512
#define Rr 8
#define SEG1 8
#define SEGD 16
static constexpr size_t FSZ = (size_t)Bn * Hn * Wn;

// packed intermediate: per channel c, (17-col sum of a_c, 17-col sum of b_c)
__device__ __half2 g_bufH[3 * FSZ];

// scalar 4B arrays: classic skew; float4 arrays: 16B-preserving skew
#define SIDX(p)  ((p) + ((p) >> 5))
#define SIDX4(p) ((p) + ((p) >> 3))

__device__ __forceinline__ float4 f4add(float4 a, float4 b) {
    return make_float4(a.x + b.x, a.y + b.y, a.z + b.z, a.w + b.w);
}
__device__ __forceinline__ float4 f4sub(float4 a, float4 b) {
    return make_float4(a.x - b.x, a.y - b.y, a.z - b.z, a.w - b.w);
}

// lo = {gr, gg, gb, gr*gy}; mid = {gg*gy, gb*gy, gr*gr, gg*gg}; hi = gb*gb
template <bool SUB>
__device__ __forceinline__ void accumV(const float* __restrict__ xb, int h, int w0,
                                       float4 vLo[4], float4 vMid[4], float vHi[4]) {
    const size_t ch = (size_t)Hn * Wn;
    size_t o = (size_t)h * Wn + w0;
    float4 x0 = __ldg((const float4*)(xb + o));
    float4 x1 = __ldg((const float4*)(xb + o + ch));
    float4 x2 = __ldg((const float4*)(xb + o + 2 * ch));
    float R[4] = {x0.x, x0.y, x0.z, x0.w};
    float G[4] = {x1.x, x1.y, x1.z, x1.w};
    float Bv[4] = {x2.x, x2.y, x2.z, x2.w};
#pragma unroll
    for (int c = 0; c < 4; ++c) {
        float gr = __saturatef(fmaf(R[c], 0.229f, 0.485f));
        float gg = __saturatef(fmaf(G[c], 0.224f, 0.456f));
        float gb = __saturatef(fmaf(Bv[c], 0.225f, 0.406f));
        float gy = (gr + gg + gb) * (1.0f / 3.0f);
        float4 dlo  = make_float4(gr, gg, gb, gr * gy);
        float4 dmid = make_float4(gg * gy, gb * gy, gr * gr, gg * gg);
        float  dhi  = gb * gb;
        if (SUB) {
            vLo[c] = f4sub(vLo[c], dlo);
            vMid[c] = f4sub(vMid[c], dmid);
            vHi[c] -= dhi;
        } else {
            vLo[c] = f4add(vLo[c], dlo);
            vMid[c] = f4add(vMid[c], dmid);
            vHi[c] += dhi;
        }
    }
}

// ---------------- Fused kernel ----------------
__global__ void __launch_bounds__(128) kF(const float* __restrict__ x) {
    __shared__ float4  sLo[600], sMid[600];   // col cc = w+8 in [0,527]
    __shared__ float   sHi[544];
    __shared__ float4  qLo[152], qMid[152];   // quad tt = t+2 in [0,131]
    __shared__ float   qHi[136];
    __shared__ __half2 abS[3][544];           // (a,b) per channel, col cc
    __shared__ __half2 qab[3][136];           // quad sums of (a,b)

    const int tid = threadIdx.x;
    const int h0  = blockIdx.x * SEG1;
    const int b   = blockIdx.y;
    const int w0  = tid * 4;
    const float* xb = x + (size_t)b * 3 * Hn * Wn;

    const float4 Z4 = make_float4(0.f, 0.f, 0.f, 0.f);
    const __half2 ZH = __floats2half2_rn(0.f, 0.f);

    if (tid < 8) {
        int cl = tid, cr = 520 + tid;
        sLo[SIDX4(cl)] = Z4;  sLo[SIDX4(cr)] = Z4;
        sMid[SIDX4(cl)] = Z4; sMid[SIDX4(cr)] = Z4;
        sHi[SIDX(cl)] = 0.f;  sHi[SIDX(cr)] = 0.f;
#pragma unroll
        for (int c = 0; c < 3; ++c) { abS[c][SIDX(cl)] = ZH; abS[c][SIDX(cr)] = ZH; }
    }
    if (tid < 2) {
        int tl = tid, tr = 130 + tid;
        qLo[SIDX4(tl)] = Z4;  qLo[SIDX4(tr)] = Z4;
        qMid[SIDX4(tl)] = Z4; qMid[SIDX4(tr)] = Z4;
        qHi[SIDX(tl)] = 0.f;  qHi[SIDX(tr)] = 0.f;
#pragma unroll
        for (int c = 0; c < 3; ++c) { qab[c][SIDX(tl)] = ZH; qab[c][SIDX(tr)] = ZH; }
    }

    float4 vLo[4], vMid[4];
    float  vHi[4];
#pragma unroll
    for (int c = 0; c < 4; ++c) { vLo[c] = Z4; vMid[c] = Z4; vHi[c] = 0.f; }

    for (int h = h0 - Rr; h < h0 + Rr; ++h)
        if (h >= 0) accumV<false>(xb, h, w0, vLo, vMid, vHi);
    __syncthreads();

    const float AREA  = 289.0f;
    const float INVA  = 1.0f / 289.0f;
    const float EPSA2 = 289.0f * 289.0f * 0.001f;

    for (int h = h0; h < h0 + SEG1; ++h) {
        int he = h + Rr;
        if (he < Hn) accumV<false>(xb, he, w0, vLo, vMid, vHi);

        // W1: publish vertical sums (field-major float4) + quads
        float4 qlo  = f4add(f4add(vLo[0], vLo[1]), f4add(vLo[2], vLo[3]));
        float4 qmid = f4add(f4add(vMid[0], vMid[1]), f4add(vMid[2], vMid[3]));
        float  qhio = (vHi[0] + vHi[1]) + (vHi[2] + vHi[3]);
#pragma unroll
        for (int c = 0; c < 4; ++c) {
            int cc = w0 + 8 + c;
            sLo[SIDX4(cc)] = vLo[c];
            sMid[SIDX4(cc)] = vMid[c];
            sHi[SIDX(cc)] = vHi[c];
        }
        qLo[SIDX4(tid + 2)] = qlo;
        qMid[SIDX4(tid + 2)] = qmid;
        qHi[SIDX(tid + 2)] = qhio;
        __syncthreads();   // S1 (also fences prev-row R2 reads of abS/qab)

        // R1: window assembly
        float4 WL = f4add(f4add(qLo[SIDX4(tid)], qLo[SIDX4(tid + 1)]),
                          f4add(qlo, qLo[SIDX4(tid + 3)]));
        WL = f4add(WL, sLo[SIDX4(w0 + 16)]);
        float4 WM = f4add(f4add(qMid[SIDX4(tid)], qMid[SIDX4(tid + 1)]),
                          f4add(qmid, qMid[SIDX4(tid + 3)]));
        WM = f4add(WM, sMid[SIDX4(w0 + 16)]);
        float WH = ((qHi[SIDX(tid)] + qHi[SIDX(tid + 1)]) + (qhio + qHi[SIDX(tid + 3)]))
                 + sHi[SIDX(w0 + 16)];

        float qa[3] = {0.f, 0.f, 0.f}, qb[3] = {0.f, 0.f, 0.f};
#pragma unroll
        for (int q = 0; q < 4; ++q) {
            float Si = (WL.x + WL.y + WL.z) * (1.0f / 3.0f);
            // channel r: Sg=WL.x, Sgi=WL.w, Sgg=WM.z
            // channel g: Sg=WL.y, Sgi=WM.x, Sgg=WM.w
            // channel b: Sg=WL.z, Sgi=WM.y, Sgg=WH
            float Sg0 = WL.x, Sg1 = WL.y, Sg2 = WL.z;
            float a0 = fmaf(AREA, WL.w, -Sg0 * Si) / (fmaf(AREA, WM.z, -Sg0 * Sg0) + EPSA2);
            float a1 = fmaf(AREA, WM.x, -Sg1 * Si) / (fmaf(AREA, WM.w, -Sg1 * Sg1) + EPSA2);
            float a2 = fmaf(AREA, WM.y, -Sg2 * Si) / (fmaf(AREA, WH,   -Sg2 * Sg2) + EPSA2);
            float b0 = (Si - a0 * Sg0) * INVA;
            float b1 = (Si - a1 * Sg1) * INVA;
            float b2 = (Si - a2 * Sg2) * INVA;
            int cc = w0 + 8 + q;
            abS[0][SIDX(cc)] = __floats2half2_rn(a0, b0);
            abS[1][SIDX(cc)] = __floats2half2_rn(a1, b1);
            abS[2][SIDX(cc)] = __floats2half2_rn(a2, b2);
            qa[0] += a0; qb[0] += b0;
            qa[1] += a1; qb[1] += b1;
            qa[2] += a2; qb[2] += b2;
            if (q < 3) {
                float4 addL = sLo[SIDX4(w0 + q + 17)], subL = sLo[SIDX4(w0 + q)];
                float4 addM = sMid[SIDX4(w0 + q + 17)], subM = sMid[SIDX4(w0 + q)];
                WL = f4sub(f4add(WL, addL), subL);
                WM = f4sub(f4add(WM, addM), subM);
                WH += sHi[SIDX(w0 + q + 17)] - sHi[SIDX(w0 + q)];
            }
        }
        __half2 qabOwn[3];
#pragma unroll
        for (int c = 0; c < 3; ++c) {
            qabOwn[c] = __floats2half2_rn(qa[c], qb[c]);
            qab[c][SIDX(tid + 2)] = qabOwn[c];
        }
        __syncthreads();   // S2

        // R2: horizontal sums of (a,b) in half2
        __align__(16) __half2 pack[3][4];
#pragma unroll
        for (int c = 0; c < 3; ++c) {
            __half2 T = __hadd2(__hadd2(qab[c][SIDX(tid)], qab[c][SIDX(tid + 1)]),
                                __hadd2(qabOwn[c], qab[c][SIDX(tid + 3)]));
            T = __hadd2(T, abS[c][SIDX(w0 + 16)]);
            pack[c][0] = T;
#pragma unroll
            for (int q = 1; q < 4; ++q) {
                T = __hsub2(__hadd2(T, abS[c][SIDX(w0 + 16 + q)]), abS[c][SIDX(w0 + q - 1)]);
                pack[c][q] = T;
            }
        }
        size_t row = ((size_t)b * Hn + h) * Wn + w0;
#pragma unroll
        for (int c = 0; c < 3; ++c)
            *(uint4*)(&g_bufH[(size_t)c * FSZ + row]) = *(const uint4*)(&pack[c][0]);

        int hl = h - Rr;
        if (hl >= 0) accumV<true>(xb, hl, w0, vLo, vMid, vHi);
    }
}

// ---------------- Kernel D: vertical sums of packed T + final combine ----------------
__global__ void __launch_bounds__(512) kD(const float* __restrict__ x, float* __restrict__ out) {
    const int w  = threadIdx.x;
    const int b  = blockIdx.z;
    const int h0 = blockIdx.y * SEGD;
    const size_t ch = (size_t)Hn * Wn;
    const size_t base = (size_t)b * Hn * Wn + w;

    float sa[3], sb[3];
#pragma unroll
    for (int c = 0; c < 3; ++c) { sa[c] = 0.0f; sb[c] = 0.0f; }

    for (int h = h0 - Rr; h < h0 + Rr; ++h) {
        if (h >= 0) {
            size_t o = base + (size_t)h * Wn;
#pragma unroll
            for (int c = 0; c < 3; ++c) {
                float2 v = __half22float2(g_bufH[(size_t)c * FSZ + o]);
                sa[c] += v.x; sb[c] += v.y;
            }
        }
    }

    const float* xb = x + (size_t)b * 3 * ch + w;
    float* ob = out + (size_t)b * 3 * ch + w;
    const float INVA = 1.0f / 289.0f;

    for (int h = h0; h < h0 + SEGD; ++h) {
        int he = h + Rr;
        if (he < Hn) {
            size_t o = base + (size_t)he * Wn;
#pragma unroll
            for (int c = 0; c < 3; ++c) {
                float2 v = __half22float2(g_bufH[(size_t)c * FSZ + o]);
                sa[c] += v.x; sb[c] += v.y;
            }
        }
        size_t o = (size_t)h * Wn;
        float xr = __ldg(xb + o);
        float xg = __ldg(xb + o + ch);
        float xv = __ldg(xb + o + 2 * ch);
        float gr = __saturatef(fmaf(xr, 0.229f, 0.485f));
        float gg = __saturatef(fmaf(xg, 0.224f, 0.456f));
        float gb = __saturatef(fmaf(xv, 0.225f, 0.406f));
        ob[o]          = gr - fmaf(sa[0], gr, sb[0]) * INVA;
        ob[o + ch]     = gg - fmaf(sa[1], gg, sb[1]) * INVA;
        ob[o + 2 * ch] = gb - fmaf(sa[2], gb, sb[2]) * INVA;
        int hl = h - Rr;
        if (hl >= 0) {
            size_t o2 = base + (size_t)hl * Wn;
#pragma unroll
            for (int c = 0; c < 3; ++c) {
                float2 v = __half22float2(g_bufH[(size_t)c * FSZ + o2]);
                sa[c] -= v.x; sb[c] -= v.y;
            }
        }
    }
}

extern "C" void kernel_launch(void* const* d_in, const int* in_sizes, int n_in,
                              void* d_out, int out_size) {
    const float* x = (const float*)d_in[0];
    float* out = (float*)d_out;
    (void)in_sizes; (void)n_in; (void)out_size;

    dim3 gF(Hn / SEG1, Bn);
    kF<<<gF, 128>>>(x);
    dim3 gD(1, Hn / SEGD, Bn);
    kD<<<gD, 512>>>(x, out);
}

// round 8
// speedup vs baseline: 3.0571x; 1.0245x over previous
#include <cuda_runtime.h>
#include <cuda_fp16.h>
#include <cstdint>

#define Bn 16
#define Hn 512
#define Wn 512
#define Rr 8
#define SEG1 16
#define SEGD 16
static constexpr size_t FSZ = (size_t)Bn * Hn * Wn;

// packed intermediate: per channel c, (17-col sum of a_c, 17-col sum of b_c)
__device__ __half2 g_bufH[3 * FSZ];

#define SIDX(p)  ((p) + ((p) >> 5))
#define SIDX4(p) ((p) + ((p) >> 3))

__device__ __forceinline__ float4 f4add(float4 a, float4 b) {
    return make_float4(a.x + b.x, a.y + b.y, a.z + b.z, a.w + b.w);
}
__device__ __forceinline__ float4 f4sub(float4 a, float4 b) {
    return make_float4(a.x - b.x, a.y - b.y, a.z - b.z, a.w - b.w);
}

// lo = {gr, gg, gb, gr*gy}; mid = {gg*gy, gb*gy, gr*gr, gg*gg}; hi = gb*gb
template <bool SUB>
__device__ __forceinline__ void accumV(const float* __restrict__ xb, int h, int w0,
                                       float4 vLo[4], float4 vMid[4], float vHi[4]) {
    const size_t ch = (size_t)Hn * Wn;
    size_t o = (size_t)h * Wn + w0;
    float4 x0 = __ldg((const float4*)(xb + o));
    float4 x1 = __ldg((const float4*)(xb + o + ch));
    float4 x2 = __ldg((const float4*)(xb + o + 2 * ch));
    float R[4] = {x0.x, x0.y, x0.z, x0.w};
    float G[4] = {x1.x, x1.y, x1.z, x1.w};
    float Bv[4] = {x2.x, x2.y, x2.z, x2.w};
#pragma unroll
    for (int c = 0; c < 4; ++c) {
        float gr = __saturatef(fmaf(R[c], 0.229f, 0.485f));
        float gg = __saturatef(fmaf(G[c], 0.224f, 0.456f));
        float gb = __saturatef(fmaf(Bv[c], 0.225f, 0.406f));
        float gy = (gr + gg + gb) * (1.0f / 3.0f);
        float4 dlo  = make_float4(gr, gg, gb, gr * gy);
        float4 dmid = make_float4(gg * gy, gb * gy, gr * gr, gg * gg);
        float  dhi  = gb * gb;
        if (SUB) {
            vLo[c] = f4sub(vLo[c], dlo);
            vMid[c] = f4sub(vMid[c], dmid);
            vHi[c] -= dhi;
        } else {
            vLo[c] = f4add(vLo[c], dlo);
            vMid[c] = f4add(vMid[c], dmid);
            vHi[c] += dhi;
        }
    }
}

// ---------------- Fused kernel ----------------
__global__ void __launch_bounds__(128) kF(const float* __restrict__ x) {
    __shared__ float4  sLo[600], sMid[600];   // col cc = w+8 in [0,527]
    __shared__ float   sHi[544];
    __shared__ float4  qLo[152], qMid[152];   // quad tt = t+2 in [0,131]
    __shared__ float   qHi[136];
    __shared__ __half2 abS[3][544];
    __shared__ __half2 qab[3][136];

    const int tid = threadIdx.x;
    const int h0  = blockIdx.x * SEG1;
    const int b   = blockIdx.y;
    const int w0  = tid * 4;
    const float* xb = x + (size_t)b * 3 * Hn * Wn;

    const float4 Z4 = make_float4(0.f, 0.f, 0.f, 0.f);
    const __half2 ZH = __floats2half2_rn(0.f, 0.f);

    if (tid < 8) {
        int cl = tid, cr = 520 + tid;
        sLo[SIDX4(cl)] = Z4;  sLo[SIDX4(cr)] = Z4;
        sMid[SIDX4(cl)] = Z4; sMid[SIDX4(cr)] = Z4;
        sHi[SIDX(cl)] = 0.f;  sHi[SIDX(cr)] = 0.f;
#pragma unroll
        for (int c = 0; c < 3; ++c) { abS[c][SIDX(cl)] = ZH; abS[c][SIDX(cr)] = ZH; }
    }
    if (tid < 2) {
        int tl = tid, tr = 130 + tid;
        qLo[SIDX4(tl)] = Z4;  qLo[SIDX4(tr)] = Z4;
        qMid[SIDX4(tl)] = Z4; qMid[SIDX4(tr)] = Z4;
        qHi[SIDX(tl)] = 0.f;  qHi[SIDX(tr)] = 0.f;
#pragma unroll
        for (int c = 0; c < 3; ++c) { qab[c][SIDX(tl)] = ZH; qab[c][SIDX(tr)] = ZH; }
    }

    float4 vLo[4], vMid[4];
    float  vHi[4];
#pragma unroll
    for (int c = 0; c < 4; ++c) { vLo[c] = Z4; vMid[c] = Z4; vHi[c] = 0.f; }

    for (int h = h0 - Rr; h < h0 + Rr; ++h)
        if (h >= 0) accumV<false>(xb, h, w0, vLo, vMid, vHi);
    __syncthreads();

    const float AREA  = 289.0f;
    const float INVA  = 1.0f / 289.0f;
    const float EPSA2 = 289.0f * 289.0f * 0.001f;

    for (int h = h0; h < h0 + SEG1; ++h) {
        int he = h + Rr;
        if (he < Hn) accumV<false>(xb, he, w0, vLo, vMid, vHi);

        // W1: publish vertical sums + quads
        float4 qlo  = f4add(f4add(vLo[0], vLo[1]), f4add(vLo[2], vLo[3]));
        float4 qmid = f4add(f4add(vMid[0], vMid[1]), f4add(vMid[2], vMid[3]));
        float  qhio = (vHi[0] + vHi[1]) + (vHi[2] + vHi[3]);
#pragma unroll
        for (int c = 0; c < 4; ++c) {
            int cc = w0 + 8 + c;
            sLo[SIDX4(cc)] = vLo[c];
            sMid[SIDX4(cc)] = vMid[c];
            sHi[SIDX(cc)] = vHi[c];
        }
        qLo[SIDX4(tid + 2)] = qlo;
        qMid[SIDX4(tid + 2)] = qmid;
        qHi[SIDX(tid + 2)] = qhio;
        __syncthreads();   // S1 (also fences prev-row R2 reads of abS/qab)

        // R1: window assembly + a/b
        float4 WL = f4add(f4add(qLo[SIDX4(tid)], qLo[SIDX4(tid + 1)]),
                          f4add(qlo, qLo[SIDX4(tid + 3)]));
        WL = f4add(WL, sLo[SIDX4(w0 + 16)]);
        float4 WM = f4add(f4add(qMid[SIDX4(tid)], qMid[SIDX4(tid + 1)]),
                          f4add(qmid, qMid[SIDX4(tid + 3)]));
        WM = f4add(WM, sMid[SIDX4(w0 + 16)]);
        float WH = ((qHi[SIDX(tid)] + qHi[SIDX(tid + 1)]) + (qhio + qHi[SIDX(tid + 3)]))
                 + sHi[SIDX(w0 + 16)];

        float qa[3] = {0.f, 0.f, 0.f}, qb[3] = {0.f, 0.f, 0.f};
#pragma unroll
        for (int q = 0; q < 4; ++q) {
            float Si = (WL.x + WL.y + WL.z) * (1.0f / 3.0f);
            float Sg0 = WL.x, Sg1 = WL.y, Sg2 = WL.z;
            float a0 = fmaf(AREA, WL.w, -Sg0 * Si) / (fmaf(AREA, WM.z, -Sg0 * Sg0) + EPSA2);
            float a1 = fmaf(AREA, WM.x, -Sg1 * Si) / (fmaf(AREA, WM.w, -Sg1 * Sg1) + EPSA2);
            float a2 = fmaf(AREA, WM.y, -Sg2 * Si) / (fmaf(AREA, WH,   -Sg2 * Sg2) + EPSA2);
            float b0 = (Si - a0 * Sg0) * INVA;
            float b1 = (Si - a1 * Sg1) * INVA;
            float b2 = (Si - a2 * Sg2) * INVA;
            int cc = w0 + 8 + q;
            abS[0][SIDX(cc)] = __floats2half2_rn(a0, b0);
            abS[1][SIDX(cc)] = __floats2half2_rn(a1, b1);
            abS[2][SIDX(cc)] = __floats2half2_rn(a2, b2);
            qa[0] += a0; qb[0] += b0;
            qa[1] += a1; qb[1] += b1;
            qa[2] += a2; qb[2] += b2;
            if (q < 3) {
                WL = f4sub(f4add(WL, sLo[SIDX4(w0 + q + 17)]), sLo[SIDX4(w0 + q)]);
                WM = f4sub(f4add(WM, sMid[SIDX4(w0 + q + 17)]), sMid[SIDX4(w0 + q)]);
                WH += sHi[SIDX(w0 + q + 17)] - sHi[SIDX(w0 + q)];
            }
        }
        __half2 qabOwn[3];
#pragma unroll
        for (int c = 0; c < 3; ++c) {
            qabOwn[c] = __floats2half2_rn(qa[c], qb[c]);
            qab[c][SIDX(tid + 2)] = qabOwn[c];
        }
        __syncthreads();   // S2

        // R2: horizontal sums of (a,b) in half2
        __align__(16) __half2 pack[3][4];
#pragma unroll
        for (int c = 0; c < 3; ++c) {
            __half2 T = __hadd2(__hadd2(qab[c][SIDX(tid)], qab[c][SIDX(tid + 1)]),
                                __hadd2(qabOwn[c], qab[c][SIDX(tid + 3)]));
            T = __hadd2(T, abS[c][SIDX(w0 + 16)]);
            pack[c][0] = T;
#pragma unroll
            for (int q = 1; q < 4; ++q) {
                T = __hsub2(__hadd2(T, abS[c][SIDX(w0 + 16 + q)]), abS[c][SIDX(w0 + q - 1)]);
                pack[c][q] = T;
            }
        }
        size_t row = ((size_t)b * Hn + h) * Wn + w0;
#pragma unroll
        for (int c = 0; c < 3; ++c)
            *(uint4*)(&g_bufH[(size_t)c * FSZ + row]) = *(const uint4*)(&pack[c][0]);

        int hl = h - Rr;
        if (hl >= 0) accumV<true>(xb, hl, w0, vLo, vMid, vHi);
    }
}

// ---------------- Kernel D: 128 threads, 2048 blocks ----------------
__global__ void __launch_bounds__(128) kD(const float* __restrict__ x, float* __restrict__ out) {
    const int w  = blockIdx.x * 128 + threadIdx.x;
    const int b  = blockIdx.z;
    const int h0 = blockIdx.y * SEGD;
    const size_t ch = (size_t)Hn * Wn;
    const size_t base = (size_t)b * Hn * Wn + w;

    float sa[3], sb[3];
#pragma unroll
    for (int c = 0; c < 3; ++c) { sa[c] = 0.0f; sb[c] = 0.0f; }

    for (int h = h0 - Rr; h < h0 + Rr; ++h) {
        if (h >= 0) {
            size_t o = base + (size_t)h * Wn;
#pragma unroll
            for (int c = 0; c < 3; ++c) {
                float2 v = __half22float2(g_bufH[(size_t)c * FSZ + o]);
                sa[c] += v.x; sb[c] += v.y;
            }
        }
    }

    const float* xb = x + (size_t)b * 3 * ch + w;
    float* ob = out + (size_t)b * 3 * ch + w;
    const float INVA = 1.0f / 289.0f;

    for (int h = h0; h < h0 + SEGD; ++h) {
        int he = h + Rr;
        if (he < Hn) {
            size_t o = base + (size_t)he * Wn;
#pragma unroll
            for (int c = 0; c < 3; ++c) {
                float2 v = __half22float2(g_bufH[(size_t)c * FSZ + o]);
                sa[c] += v.x; sb[c] += v.y;
            }
        }
        size_t o = (size_t)h * Wn;
        float xr = __ldg(xb + o);
        float xg = __ldg(xb + o + ch);
        float xv = __ldg(xb + o + 2 * ch);
        float gr = __saturatef(fmaf(xr, 0.229f, 0.485f));
        float gg = __saturatef(fmaf(xg, 0.224f, 0.456f));
        float gb = __saturatef(fmaf(xv, 0.225f, 0.406f));
        ob[o]          = gr - fmaf(sa[0], gr, sb[0]) * INVA;
        ob[o + ch]     = gg - fmaf(sa[1], gg, sb[1]) * INVA;
        ob[o + 2 * ch] = gb - fmaf(sa[2], gb, sb[2]) * INVA;
        int hl = h - Rr;
        if (hl >= 0) {
            size_t o2 = base + (size_t)hl * Wn;
#pragma unroll
            for (int c = 0; c < 3; ++c) {
                float2 v = __half22float2(g_bufH[(size_t)c * FSZ + o2]);
                sa[c] -= v.x; sb[c] -= v.y;
            }
        }
    }
}

extern "C" void kernel_launch(void* const* d_in, const int* in_sizes, int n_in,
                              void* d_out, int out_size) {
    const float* x = (const float*)d_in[0];
    float* out = (float*)d_out;
    (void)in_sizes; (void)n_in; (void)out_size;

    dim3 gF(Hn / SEG1, Bn);
    kF<<<gF, 128>>>(x);
    dim3 gD(Wn / 128, Hn / SEGD, Bn);
    kD<<<gD, 128>>>(x, out);
}